// round 2
// baseline (speedup 1.0000x reference)
#include <cuda_runtime.h>
#include <cstdint>
#include <cstddef>

#define SEQ   512
#define BATCH 64
#define INDIM 128
#define HDIM  512

// ---------------- recurrent kernel configuration ----------------
#define GB 8     // batch-tile blocks
#define GJ 16    // j-tile blocks  (GB*GJ = 128 blocks, all co-resident)
#define BT 8     // batch rows per block   (64/GB)
#define JT 32    // h columns per block    (512/GJ)
#define RTHREADS 256

// step-ping-pong hidden state + per-block completion flags (device globals: no allocs)
__device__ float g_h[2][BATCH][HDIM];
__device__ int   g_flag[GB][GJ];

__device__ __forceinline__ int ld_acquire(const int* p) {
    int v;
    asm volatile("ld.global.acquire.gpu.s32 %0, [%1];" : "=r"(v) : "l"(p) : "memory");
    return v;
}
__device__ __forceinline__ void st_release(int* p, int v) {
    asm volatile("st.global.release.gpu.s32 [%0], %1;" :: "l"(p), "r"(v) : "memory");
}

__global__ void reset_flags_kernel() {
    int t = threadIdx.x;
    if (t < GB * GJ) ((int*)g_flag)[t] = 0;
}

// ---------------------------------------------------------------------------
// xi kernel: out[s][b][h] = sum_k x[s][b][k] * Wi[h][k] + bi[h]
// Written straight into d_out (h_seq region); recurrent kernel reads it in
// place and overwrites with h_t.
// Block tile: 32 (s*b) rows x 128 h cols, full K=128 per thread (no reduction).
// Thread tile 4x4; lanes interleaved over h (h = j*32 + tx) so with SMEM row
// stride 129 the Wi shared loads are bank-conflict-free (bank = (tx+k)%32).
// ---------------------------------------------------------------------------
__global__ __launch_bounds__(256) void xi_kernel(
    const float* __restrict__ x, const float* __restrict__ Wi,
    const float* __restrict__ bi, float* __restrict__ out)
{
    extern __shared__ float sm[];
    float* ws = sm;               // [128][129]
    float* xs = sm + 128 * 129;   // [32][129]

    const int tid = threadIdx.x;
    const int sb0 = blockIdx.x * 32;   // 1024 tiles over 32768 (s*b) rows
    const int h0  = blockIdx.y * 128;  // 4 tiles over 512 h

    for (int i = tid; i < 128 * INDIM; i += 256) {
        int r = i >> 7, k = i & 127;
        ws[r * 129 + k] = Wi[(h0 + r) * INDIM + k];
    }
    for (int i = tid; i < 32 * INDIM; i += 256) {
        int r = i >> 7, k = i & 127;
        xs[r * 129 + k] = x[(size_t)(sb0 + r) * INDIM + k];
    }
    __syncthreads();

    const int ty = tid >> 5;   // 0..7  -> sb rows ty*4..+3
    const int tx = tid & 31;   // 0..31 -> h = j*32 + tx

    float acc[4][4];
#pragma unroll
    for (int i = 0; i < 4; i++)
#pragma unroll
        for (int j = 0; j < 4; j++) acc[i][j] = 0.f;

    const float* xb = xs + (ty * 4) * 129;
#pragma unroll 4
    for (int k = 0; k < INDIM; k++) {
        float xv[4], wv[4];
#pragma unroll
        for (int i = 0; i < 4; i++) xv[i] = xb[i * 129 + k];
#pragma unroll
        for (int j = 0; j < 4; j++) wv[j] = ws[(j * 32 + tx) * 129 + k];
#pragma unroll
        for (int i = 0; i < 4; i++)
#pragma unroll
            for (int j = 0; j < 4; j++) acc[i][j] += xv[i] * wv[j];
    }

#pragma unroll
    for (int j = 0; j < 4; j++) {
        int h = h0 + j * 32 + tx;
        float b = bi[h];
#pragma unroll
        for (int i = 0; i < 4; i++) {
            out[(size_t)(sb0 + ty * 4 + i) * HDIM + h] = acc[i][j] + b;
        }
    }
}

// ---------------------------------------------------------------------------
// Persistent recurrent kernel. 128 blocks = (bt in 0..7) x (jt in 0..15).
// Block (bt,jt) owns output chunk h[bt*8 .. +8][jt*32 .. +32] each step.
// Wh tile (32 rows x 512) resident in SMEM for all 512 steps.
// Per step it needs h_{t-1}[its 8 batch rows][all 512 k] = the 16 chunks
// produced by blocks (bt, *): waits on 16 L2 flags, loads 16KB of h.
// Compute: 8 warps, warp tile 4b x 8j, lanes = k-slice (k = kk*32 + lane,
// bank-conflict-free SMEM), 32 fp32 accumulators/thread, then a padded
// shared-memory 32-lane reduction (conflict-free via stride 33).
// ---------------------------------------------------------------------------
__global__ __launch_bounds__(RTHREADS, 1) void rnn_kernel(
    const float* __restrict__ Wh, const float* __restrict__ bh, float* out)
{
    extern __shared__ float sm[];
    float* sWh = sm;                         // [32][512]  64KB, persistent
    float* sh  = sm + JT * HDIM;             // [8][512]   16KB, per-step h
    float* red = sm + JT * HDIM + BT * HDIM; // [8][32][33] reduction scratch

    const int tid  = threadIdx.x;
    const int bt   = blockIdx.x >> 4;
    const int jt   = blockIdx.x & 15;

    // load Wh tile once (rows jt*32 .. +31, contiguous)
    {
        const float4* src = (const float4*)(Wh + (size_t)jt * JT * HDIM);
        float4* dst = (float4*)sWh;
        for (int i = tid; i < JT * HDIM / 4; i += RTHREADS) dst[i] = src[i];
    }

    const int w    = tid >> 5;       // warp 0..7
    const int lane = tid & 31;       // k-slice lane
    const int tr   = w >> 2;         // 0..1 batch half
    const int tc   = w & 3;          // 0..3 j quarter

    // this lane's final output element (after 32-lane reduction): v = lane
    const int ob = bt * BT + tr * 4 + (lane >> 3);
    const int oj = jt * JT + tc * 8 + (lane & 7);
    const float bhv = bh[oj];

    float* rw = red + w * 32 * 33;
    const float* hb = sh  + (tr * 4) * HDIM;
    const float* wb = sWh + (tc * 8) * HDIM;

    __syncthreads();

    for (int t = 1; t <= SEQ; t++) {
        const size_t oidx = (size_t)(t - 1) * (BATCH * HDIM) + (size_t)ob * HDIM + oj;
        // prefetch xi for this step early (independent of h, hides DRAM latency)
        const float xiv = out[oidx];

        float sum = 0.f;
        if (t > 1) {
            // wait for the 16 producer blocks of our batch rows (step t-1)
            if (tid < GJ) {
                while (ld_acquire(&g_flag[bt][tid]) < t - 1) { }
            }
            __syncthreads();

            // stage h_{t-1}[bt*8 .. +8][:] into shared (contiguous 16KB)
            {
                const float4* src = (const float4*)&g_h[(t - 1) & 1][bt * BT][0];
                float4* dst = (float4*)sh;
                for (int i = tid; i < BT * HDIM / 4; i += RTHREADS) dst[i] = src[i];
            }
            __syncthreads();

            float acc[4][8];
#pragma unroll
            for (int i = 0; i < 4; i++)
#pragma unroll
                for (int j = 0; j < 8; j++) acc[i][j] = 0.f;

#pragma unroll
            for (int kk = 0; kk < 16; kk++) {
                const int k = kk * 32 + lane;
                float hv[4], wv[8];
#pragma unroll
                for (int i = 0; i < 4; i++) hv[i] = hb[i * HDIM + k];
#pragma unroll
                for (int j = 0; j < 8; j++) wv[j] = wb[j * HDIM + k];
#pragma unroll
                for (int i = 0; i < 4; i++)
#pragma unroll
                    for (int j = 0; j < 8; j++) acc[i][j] += hv[i] * wv[j];
            }

            // 32-lane split-k reduction through padded shared (conflict-free)
#pragma unroll
            for (int v = 0; v < 32; v++) rw[v * 33 + lane] = acc[v >> 3][v & 7];
            __syncwarp();
#pragma unroll
            for (int i = 0; i < 32; i++) sum += rw[lane * 33 + i];
        }

        const float hval = tanhf(sum + bhv + xiv);

        out[oidx] = hval;                 // h_seq[t-1]
        g_h[t & 1][ob][oj] = hval;        // ping-pong state for step t+1
        if (t == SEQ) out[(size_t)SEQ * BATCH * HDIM + (size_t)ob * HDIM + oj] = hval; // h_last

        __threadfence();                  // make writes GPU-visible
        __syncthreads();                  // all threads of block fenced
        if (tid == 0) st_release(&g_flag[bt][jt], t);
    }
}

// ---------------------------------------------------------------------------
extern "C" void kernel_launch(void* const* d_in, const int* in_sizes, int n_in,
                              void* d_out, int out_size)
{
    const float* x  = (const float*)d_in[0];
    const float* Wi = (const float*)d_in[1];
    const float* bi = (const float*)d_in[2];
    const float* Wh = (const float*)d_in[3];
    const float* bh = (const float*)d_in[4];
    float* out = (float*)d_out;

    const int XI_SMEM  = (128 * 129 + 32 * 129) * 4;              // 82560 B
    const int RNN_SMEM = (JT * HDIM + BT * HDIM + 8 * 32 * 33) * 4; // 115712 B

    cudaFuncSetAttribute(xi_kernel,  cudaFuncAttributeMaxDynamicSharedMemorySize, XI_SMEM);
    cudaFuncSetAttribute(rnn_kernel, cudaFuncAttributeMaxDynamicSharedMemorySize, RNN_SMEM);

    // 1) reset cross-block flags (graph replays reuse the device globals)
    reset_flags_kernel<<<1, 128>>>();
    // 2) input projection for all timesteps, written into d_out in place
    xi_kernel<<<dim3(32768 / 32, HDIM / 128), 256, XI_SMEM>>>(x, Wi, bi, out);
    // 3) persistent recurrence: 128 co-resident blocks, flag-synced per step
    rnn_kernel<<<GB * GJ, RTHREADS, RNN_SMEM>>>(Wh, bh, out);
}